// round 8
// baseline (speedup 1.0000x reference)
#include <cuda_runtime.h>

// DeformableCONV: modulated deformable conv v2, depthwise (groups = C).
// x:       (B, C, H, W)           f32
// offsets: (B, 2*C*KK, H, W)      f32   layout (B, C, KK, 2{dy,dx}, H, W)
// mask:    (B, C*KK, H, W)        f32   layout (B, C, KK, H, W)
// weight:  (C, 1, K, K)           f32
// bias:    (C,)                   f32
// out:     (B, C, H, W)           f32

#define B_ 32
#define C_ 17
#define H_ 96
#define W_ 72
#define KK_ 9
#define HW_ (H_ * W_)           // 6912
#define NTHREADS 256
#define SPLIT 6
#define R_ (H_ / SPLIT)         // 16 output rows per CTA
#define PIX_PER (HW_ / SPLIT)   // 1152
#define M_ 8                    // staging margin (max |offset| ~6 on N(0,1) data)
#define BW_ (W_ + 3)            // 75 padded cols: 0 zero, 1..72 data, 73,74 zero
#define BH_ (R_ + 2 * M_ + 3)   // 35 padded band rows
// Band row j holds padded-global row g = G0 + j, G0 = r0 - M_.
// Gathers for output rows [r0, r0+R_) touch padded rows [r0-7, r0+R_+9],
// all inside the band for |offset| <= 9.5; anything beyond takes the exact
// global-memory fallback below.

__global__ __launch_bounds__(NTHREADS, 6)
void dcn_kernel(const float* __restrict__ x,
                const float* __restrict__ off,
                const float* __restrict__ mask,
                const float* __restrict__ weight,
                const float* __restrict__ bias,
                float* __restrict__ out)
{
    __shared__ float band[BH_ * BW_];   // 10,500 B zero-padded band

    const int s  = blockIdx.x;          // band index 0..SPLIT-1
    const int bc = blockIdx.y;          // b * C_ + c
    const int c  = bc % C_;
    const int b  = bc / C_;
    const int tid = threadIdx.x;

    const int r0 = s * R_;
    const int G0 = r0 - M_;             // padded-global row of band row 0

    // Zero the band, then fill interior rows present in [1, 96].
    #pragma unroll
    for (int i = tid; i < BH_ * BW_; i += NTHREADS)
        band[i] = 0.0f;

    float wk[KK_];
    #pragma unroll
    for (int k = 0; k < KK_; ++k)
        wk[k] = weight[c * KK_ + k];
    const float bv = bias[c];

    __syncthreads();

    const float* __restrict__ xp = x + (size_t)bc * HW_;
    {
        const int g_lo = max(1, G0);
        const int g_hi = min(H_, G0 + BH_ - 1);
        const int nr   = g_hi - g_lo + 1;
        for (int i = tid; i < nr * W_; i += NTHREADS) {
            const int rr = i / W_;
            const int cc = i - rr * W_;
            const int g  = g_lo + rr;
            band[(g - G0) * BW_ + cc + 1] = xp[(g - 1) * W_ + cc];
        }
    }
    __syncthreads();

    const float* __restrict__ offb = off  + (size_t)b * (2 * C_ * KK_ * HW_)
                                          + (size_t)(c * KK_) * 2 * HW_;
    const float* __restrict__ mb   = mask + (size_t)b * (C_ * KK_ * HW_)
                                          + (size_t)(c * KK_) * HW_;
    float* __restrict__ op = out + (size_t)bc * HW_;

    const int p0   = s * PIX_PER + tid;
    const int pend = (s + 1) * PIX_PER;

    int h = p0 / W_;
    int w = p0 - h * W_;
    // stride 256 = 3*W_ + 40
    for (int p = p0; p < pend; p += NTHREADS) {
        float acc = 0.0f;

        #pragma unroll
        for (int k = 0; k < KK_; ++k) {
            const float dy = __ldcs(offb + (size_t)(2 * k    ) * HW_ + p);
            const float dx = __ldcs(offb + (size_t)(2 * k + 1) * HW_ + p);
            const float m  = __ldcs(mb   + (size_t)k           * HW_ + p);

            const int ky = k / 3;
            const int kx = k - ky * 3;

            // Clamp to [-1, H]/[-1, W]: exact (weight of any real texel is 0
            // at/past the clamp, padding reads 0).
            float py = fminf(fmaxf((float)(h - 1 + ky) + dy, -1.0f), (float)H_);
            float px = fminf(fmaxf((float)(w - 1 + kx) + dx, -1.0f), (float)W_);

            const float y0f = floorf(py);
            const float x0f = floorf(px);
            const float wy = py - y0f;
            const float wx = px - x0f;

            const int j  = (int)y0f + 1 - G0;   // band row of top corner
            const int xi = (int)x0f + 1;        // padded col of left corner

            float v;
            if ((unsigned)j <= (unsigned)(BH_ - 2)) {
                // Hot path: branchless bilinear from the band (unit-stride
                // addresses across the warp -> minimal bank conflicts).
                const int idx = j * BW_ + xi;
                const float s00 = band[idx];
                const float s01 = band[idx + 1];
                const float s10 = band[idx + BW_];
                const float s11 = band[idx + BW_ + 1];
                const float vt = fmaf(wx, s01 - s00, s00);
                const float vb = fmaf(wx, s11 - s10, s10);
                v = fmaf(wy, vb - vt, vt);
            } else {
                // Cold exact fallback (|offset| > ~9: never on this data,
                // but correctness does not depend on that).
                const int y0 = (int)y0f, x0 = (int)x0f;
                const int y1 = y0 + 1,  x1 = x0 + 1;
                const bool vy0 = (unsigned)y0 < (unsigned)H_;
                const bool vy1 = (unsigned)y1 < (unsigned)H_;
                const bool vx0 = (unsigned)x0 < (unsigned)W_;
                const bool vx1 = (unsigned)x1 < (unsigned)W_;
                const int cy0 = min(max(y0, 0), H_ - 1);
                const int cy1 = min(max(y1, 0), H_ - 1);
                const int cx0 = min(max(x0, 0), W_ - 1);
                const int cx1 = min(max(x1, 0), W_ - 1);
                v = 0.0f;
                if (vy0 & vx0) v = fmaf(xp[cy0 * W_ + cx0], (1.0f - wy) * (1.0f - wx), v);
                if (vy0 & vx1) v = fmaf(xp[cy0 * W_ + cx1], (1.0f - wy) * wx, v);
                if (vy1 & vx0) v = fmaf(xp[cy1 * W_ + cx0], wy * (1.0f - wx), v);
                if (vy1 & vx1) v = fmaf(xp[cy1 * W_ + cx1], wy * wx, v);
            }

            acc = fmaf(m * v, wk[k], acc);
        }

        __stcs(op + p, acc + bv);

        // advance (h, w) by 256 pixels: 256 = 3*W_ + 40
        h += 3; w += 40;
        if (w >= W_) { w -= W_; ++h; }
    }
}

extern "C" void kernel_launch(void* const* d_in, const int* in_sizes, int n_in,
                              void* d_out, int out_size)
{
    const float* x      = (const float*)d_in[0];
    const float* off    = (const float*)d_in[1];
    const float* mask   = (const float*)d_in[2];
    const float* weight = (const float*)d_in[3];
    const float* bias   = (const float*)d_in[4];
    float* out          = (float*)d_out;

    dim3 grid(SPLIT, B_ * C_);
    dcn_kernel<<<grid, NTHREADS>>>(x, off, mask, weight, bias, out);
}

// round 9
// speedup vs baseline: 1.4884x; 1.4884x over previous
#include <cuda_runtime.h>

// DeformableCONV: modulated deformable conv v2, depthwise (groups = C).
// x:       (B, C, H, W)           f32
// offsets: (B, 2*C*KK, H, W)      f32   layout (B, C, KK, 2{dy,dx}, H, W)
// mask:    (B, C*KK, H, W)        f32   layout (B, C, KK, H, W)
// weight:  (C, 1, K, K)           f32
// bias:    (C,)                   f32
// out:     (B, C, H, W)           f32

#define B_ 32
#define C_ 17
#define H_ 96
#define W_ 72
#define KK_ 9
#define HW_ (H_ * W_)           // 6912
#define NTHREADS 256
#define SPLIT 3
#define PIX_PER (HW_ / SPLIT)   // 2304 = 9 * 256
#define PW (W_ + 3)             // 75: col 0 zero, cols 1..72 data, 73,74 zero
#define PH (H_ + 3)             // 99: row 0 zero, rows 1..96 data, 97,98 zero

// Branchless bilinear gather from zero-padded smem plane.
// Clamping py to [-1, H] / px to [-1, W] is exact: at/beyond the clamp every
// real texel's interpolation weight is 0 and the padding reads 0.
__device__ __forceinline__ float bilerp(const float* __restrict__ sx,
                                        float py, float px)
{
    py = fminf(fmaxf(py, -1.0f), (float)H_);
    px = fminf(fmaxf(px, -1.0f), (float)W_);
    const float y0f = floorf(py);
    const float x0f = floorf(px);
    const float wy = py - y0f;
    const float wx = px - x0f;
    const int idx = ((int)y0f + 1) * PW + ((int)x0f + 1);
    const float s00 = sx[idx];
    const float s01 = sx[idx + 1];
    const float s10 = sx[idx + PW];
    const float s11 = sx[idx + PW + 1];
    const float vt = fmaf(wx, s01 - s00, s00);
    const float vb = fmaf(wx, s11 - s10, s10);
    return fmaf(wy, vb - vt, vt);
}

__global__ __launch_bounds__(NTHREADS, 6)
void dcn_kernel(const float* __restrict__ x,
                const float* __restrict__ off,
                const float* __restrict__ mask,
                const float* __restrict__ weight,
                const float* __restrict__ bias,
                float* __restrict__ out)
{
    __shared__ float sx[PH * PW];       // 29,700 B zero-padded (b,c) plane

    const int s  = blockIdx.x;          // plane split index 0..SPLIT-1
    const int bc = blockIdx.y;          // b * C_ + c
    const int c  = bc % C_;
    const int b  = bc / C_;
    const int tid = threadIdx.x;

    // Zero the padded plane, then fill interior. Sibling CTAs (same bc,
    // different s) are adjacent in the grid -> x plane hits L2 after 1st read.
    #pragma unroll
    for (int i = tid; i < PH * PW; i += NTHREADS)
        sx[i] = 0.0f;

    float wk[KK_];
    #pragma unroll
    for (int k = 0; k < KK_; ++k)
        wk[k] = weight[c * KK_ + k];
    const float bv = bias[c];

    __syncthreads();

    const float* __restrict__ xp = x + (size_t)bc * HW_;
    #pragma unroll
    for (int i = tid; i < HW_; i += NTHREADS) {
        const int r = i / W_;
        const int cc = i - r * W_;
        sx[(r + 1) * PW + (cc + 1)] = xp[i];
    }
    __syncthreads();

    const float* __restrict__ offb = off  + (size_t)b * (2 * C_ * KK_ * HW_)
                                          + (size_t)(c * KK_) * 2 * HW_;
    const float* __restrict__ mb   = mask + (size_t)b * (C_ * KK_ * HW_)
                                          + (size_t)(c * KK_) * HW_;
    float* __restrict__ op = out + (size_t)bc * HW_;

    // Scalar pixels: p = p0 + 256*i -> gather addresses are unit-stride
    // across the warp (conflict-free LDS). 9 pixels per thread.
    const int p0   = s * PIX_PER + tid;
    const int pend = (s + 1) * PIX_PER;

    int h = p0 / W_;
    int w = p0 - h * W_;
    // stride 256 = 3*W_ + 40
    for (int p = p0; p < pend; p += NTHREADS) {
        // Front-batched loads (fully unrolled, no branches -> high MLP).
        float dy[KK_], dx[KK_], m[KK_];
        #pragma unroll
        for (int k = 0; k < KK_; ++k) {
            dy[k] = __ldcs(offb + (size_t)(2 * k    ) * HW_ + p);
            dx[k] = __ldcs(offb + (size_t)(2 * k + 1) * HW_ + p);
            m[k]  = __ldcs(mb   + (size_t)k           * HW_ + p);
        }

        const float hy  = (float)(h - 1);
        const float wxx = (float)(w - 1);

        float acc = 0.0f;
        #pragma unroll
        for (int k = 0; k < KK_; ++k) {
            const int ky = k / 3;
            const int kx = k - ky * 3;
            const float v = bilerp(sx, hy + (float)ky + dy[k],
                                       wxx + (float)kx + dx[k]);
            acc = fmaf(m[k] * v, wk[k], acc);
        }

        __stcs(op + p, acc + bv);

        // advance (h, w) by 256 pixels: 256 = 3*W_ + 40
        h += 3; w += 40;
        if (w >= W_) { w -= W_; ++h; }
    }
}

extern "C" void kernel_launch(void* const* d_in, const int* in_sizes, int n_in,
                              void* d_out, int out_size)
{
    const float* x      = (const float*)d_in[0];
    const float* off    = (const float*)d_in[1];
    const float* mask   = (const float*)d_in[2];
    const float* weight = (const float*)d_in[3];
    const float* bias   = (const float*)d_in[4];
    float* out          = (float*)d_out;

    dim3 grid(SPLIT, B_ * C_);
    dcn_kernel<<<grid, NTHREADS>>>(x, off, mask, weight, bias, out);
}